// round 7
// baseline (speedup 1.0000x reference)
#include <cuda_runtime.h>
#include <math.h>

#define VV 3
#define CC 32
#define DD 48
#define HH 128
#define WW 160
#define HW (HH*WW)        /* 20480 */
#define DHW (DD*HW)       /* 983040 */

// ---------------------------------------------------------------------------
// Scratch
// ---------------------------------------------------------------------------
__device__ float g_xform[2][12];
__device__ float g_feat_t[(size_t)VV*HW*CC];     // channels-last features
__device__ float g_var[(size_t)DHW*CC];          // variance, PAIR-PERMUTED + tf32
__device__ float g_h0[(size_t)DHW*8];            // conv0 out [D,H,W,8] plain
__device__ float g_h1[(size_t)DHW*8];            // conv1 out [D,H,W,8] plain
__device__ float g_cost[(size_t)DHW];            // conv2 out [D,H,W]

__device__ __forceinline__ unsigned tf32cvt(float f) {
    unsigned u;
    asm("cvt.rna.tf32.f32 %0, %1;" : "=r"(u) : "f"(f));
    return u;
}

// D(16x8) += A(16x8) * B(8x8), tf32 operands, f32 accum
__device__ __forceinline__ void mma_tf32(float* d, const unsigned* a, const unsigned* b) {
    asm("mma.sync.aligned.m16n8k8.row.col.f32.tf32.tf32.f32 "
        "{%0,%1,%2,%3}, {%4,%5,%6,%7}, {%8,%9}, {%0,%1,%2,%3};"
        : "+f"(d[0]), "+f"(d[1]), "+f"(d[2]), "+f"(d[3])
        : "r"(a[0]), "r"(a[1]), "r"(a[2]), "r"(a[3]), "r"(b[0]), "r"(b[1]));
}

// ---------------------------------------------------------------------------
// Kernel 1: projective transforms  M_v = C_v * inv(C_0)
// ---------------------------------------------------------------------------
__global__ void k_xform(const float* __restrict__ proj) {
    if (threadIdx.x || blockIdx.x) return;
    double Cm[3][4][4];
    for (int v = 0; v < 3; ++v) {
        double K[3][3], E[4][4];
        for (int i = 0; i < 3; ++i)
            for (int j = 0; j < 3; ++j)
                K[i][j] = (double)proj[((v*2+1)*4+i)*4+j];
        for (int i = 0; i < 4; ++i)
            for (int j = 0; j < 4; ++j)
                E[i][j] = (double)proj[((v*2+0)*4+i)*4+j];
        for (int i = 0; i < 3; ++i)
            for (int j = 0; j < 4; ++j) {
                double s = 0.0;
                for (int k = 0; k < 3; ++k) s += K[i][k]*E[k][j];
                Cm[v][i][j] = s;
            }
        for (int j = 0; j < 4; ++j) Cm[v][3][j] = E[3][j];
    }
    double A[4][8];
    for (int i = 0; i < 4; ++i)
        for (int j = 0; j < 4; ++j) { A[i][j] = Cm[0][i][j]; A[i][4+j] = (i==j) ? 1.0 : 0.0; }
    for (int col = 0; col < 4; ++col) {
        int piv = col;
        for (int r = col+1; r < 4; ++r) if (fabs(A[r][col]) > fabs(A[piv][col])) piv = r;
        if (piv != col)
            for (int j = 0; j < 8; ++j) { double t = A[col][j]; A[col][j] = A[piv][j]; A[piv][j] = t; }
        double iv = 1.0 / A[col][col];
        for (int j = 0; j < 8; ++j) A[col][j] *= iv;
        for (int r = 0; r < 4; ++r) if (r != col) {
            double f = A[r][col];
            for (int j = 0; j < 8; ++j) A[r][j] -= f * A[col][j];
        }
    }
    for (int v = 1; v < 3; ++v) {
        double M[3][4];
        for (int i = 0; i < 3; ++i)
            for (int j = 0; j < 4; ++j) {
                double s = 0.0;
                for (int k = 0; k < 4; ++k) s += Cm[v][i][k] * A[k][4+j];
                M[i][j] = s;
            }
        float* o = g_xform[v-1];
        o[0]=(float)M[0][0]; o[1]=(float)M[0][1]; o[2]=(float)M[0][2];
        o[3]=(float)M[1][0]; o[4]=(float)M[1][1]; o[5]=(float)M[1][2];
        o[6]=(float)M[2][0]; o[7]=(float)M[2][1]; o[8]=(float)M[2][2];
        o[9]=(float)M[0][3]; o[10]=(float)M[1][3]; o[11]=(float)M[2][3];
    }
}

// ---------------------------------------------------------------------------
// Kernel 2: tiled transpose [V,C,H,W] -> [V,H,W,C]
// ---------------------------------------------------------------------------
__global__ void k_transpose(const float* __restrict__ f) {
    __shared__ float t[32][33];
    int v   = blockIdx.y;
    int hw0 = blockIdx.x * 32;
    for (int i = threadIdx.y; i < 32; i += 8)
        t[i][threadIdx.x] = f[((size_t)v*32 + i)*HW + hw0 + threadIdx.x];
    __syncthreads();
    for (int i = threadIdx.y; i < 32; i += 8)
        g_feat_t[((size_t)v*HW + hw0 + i)*32 + threadIdx.x] = t[threadIdx.x][i];
}

// ---------------------------------------------------------------------------
// Kernel 3: warp+variance. Output: pair-permuted ([0,4,1,5,2,6,3,7] per 8-chunk)
// and tf32-pre-rounded (g_var feeds only conv0).
// ---------------------------------------------------------------------------
__global__ void __launch_bounds__(256) k_warpvar(const float* __restrict__ dvals) {
    long long t = (long long)blockIdx.x*256 + threadIdx.x;
    int g   = (int)(t & 7);
    int idx = (int)(t >> 3);
    if (idx >= DHW) return;
    int w = idx % WW;
    int h = (idx / WW) % HH;
    float depth = dvals[idx];

    int   offs[2][4];
    float cwts[2][4];
    #pragma unroll
    for (int v = 0; v < 2; ++v) {
        const float* xf = g_xform[v];
        float x = (float)w, y = (float)h;
        float rx = xf[0]*x + xf[1]*y + xf[2];
        float ry = xf[3]*x + xf[4]*y + xf[5];
        float rz = xf[6]*x + xf[7]*y + xf[8];
        float px = rx*depth + xf[9];
        float py = ry*depth + xf[10];
        float pz = rz*depth + xf[11];
        float gx = px / pz / ((float)(WW-1)*0.5f) - 1.0f;
        float gy = py / pz / ((float)(HH-1)*0.5f) - 1.0f;
        float sx = (gx + 1.0f) * 0.5f * (float)(WW-1);
        float sy = (gy + 1.0f) * 0.5f * (float)(HH-1);
        float x0 = floorf(sx), y0 = floorf(sy);
        float wx1 = sx - x0, wx0 = 1.0f - wx1;
        float wy1 = sy - y0, wy0 = 1.0f - wy1;
        float cx[2] = {x0, x0+1.0f}, cy[2] = {y0, y0+1.0f};
        float wx[2] = {wx0, wx1}, wy[2] = {wy0, wy1};
        #pragma unroll
        for (int cyi = 0; cyi < 2; ++cyi)
        #pragma unroll
        for (int cxi = 0; cxi < 2; ++cxi) {
            float xi = cx[cxi], yi = cy[cyi];
            bool valid = (xi >= 0.0f) && (xi <= (float)(WW-1)) &&
                         (yi >= 0.0f) && (yi <= (float)(HH-1));
            float xc = fminf(fmaxf(xi, 0.0f), (float)(WW-1));
            float yc = fminf(fmaxf(yi, 0.0f), (float)(HH-1));
            int ii = (int)yc * WW + (int)xc;
            offs[v][cyi*2+cxi] = ii * CC + g*4;
            cwts[v][cyi*2+cxi] = wx[cxi]*wy[cyi] * (valid ? 1.0f : 0.0f);
        }
    }

    float4 r = *(const float4*)(g_feat_t + (size_t)(h*WW + w)*CC + g*4);
    const float* s1 = g_feat_t + (size_t)HW*CC;
    const float* s2 = g_feat_t + (size_t)2*HW*CC;

    float sx_ = r.x, sy_ = r.y, sz_ = r.z, sw_ = r.w;
    float qx = r.x*r.x, qy = r.y*r.y, qz = r.z*r.z, qw = r.w*r.w;
    #pragma unroll
    for (int v = 0; v < 2; ++v) {
        const float* base = (v == 0) ? s1 : s2;
        float wxp = 0.f, wyp = 0.f, wzp = 0.f, wwp = 0.f;
        #pragma unroll
        for (int k = 0; k < 4; ++k) {
            float cw = cwts[v][k];
            const float4 f = *(const float4*)(base + offs[v][k]);
            wxp = fmaf(cw, f.x, wxp);
            wyp = fmaf(cw, f.y, wyp);
            wzp = fmaf(cw, f.z, wzp);
            wwp = fmaf(cw, f.w, wwp);
        }
        sx_ += wxp; sy_ += wyp; sz_ += wzp; sw_ += wwp;
        qx = fmaf(wxp, wxp, qx); qy = fmaf(wyp, wyp, qy);
        qz = fmaf(wzp, wzp, qz); qw = fmaf(wwp, wwp, qw);
    }
    float vals[4];
    float mx = sx_ / 3.0f, my = sy_ / 3.0f, mz = sz_ / 3.0f, mw = sw_ / 3.0f;
    vals[0] = qx / 3.0f - mx*mx;
    vals[1] = qy / 3.0f - my*my;
    vals[2] = qz / 3.0f - mz*mz;
    vals[3] = qw / 3.0f - mw*mw;
    // permuted write: orig ch 4g+j -> chunk g>>1, slot 2j + (g&1)
    float* outb = g_var + (size_t)idx*CC + (g >> 1)*8 + (g & 1);
    #pragma unroll
    for (int j = 0; j < 4; ++j)
        outb[2*j] = __uint_as_float(tf32cvt(vals[j]));
}

// ---------------------------------------------------------------------------
// Kernel 4: conv0 (32->8) tf32 mma. Pair-permuted slab, float2 fragment loads,
// software-pipelined c-loop. 256 thr, 8 warps, DS=6.
// ---------------------------------------------------------------------------
__global__ void __launch_bounds__(256, 1)
k_conv0(const float* __restrict__ wgt, const float* __restrict__ bias) {
    constexpr int DS = 6, NSL = 8;
    constexpr int SLICE = 10*18*32;               // 5760 floats

    extern __shared__ float sm[];
    float* s_w  = sm;                             // [tap][cin 32][co 8] tf32
    float* slab = sm + 27*32*8;

    const int tid  = threadIdx.x;
    const int ty   = tid >> 5;                    // warp id = h row 0..7
    const int lane = tid & 31;
    const int gid  = lane >> 2;
    const int tig  = lane & 3;
    const int w0 = blockIdx.x * 16;
    const int h0 = blockIdx.y * 8;
    const int d0 = blockIdx.z * DS;

    // weights: s_w[tap*256 + cin*8 + co] (cin ORIGINAL order; pair trick keeps k==cin)
    for (int i = tid; i < 27*256; i += 256) {
        int co  = i & 7;
        int cin = (i >> 3) & 31;
        int tap = i >> 8;
        ((unsigned*)s_w)[i] = tf32cvt(wgt[(co*32 + cin)*27 + tap]);
    }
    // slab fill: g_var is already tf32 + pair-permuted. float4 q4 covers pairs
    // (2q4, 2q4+1); store at swizzled pair position f = p ^ ((pix&3)<<2).
    {
        const int NTOT = NSL*10*18*8;
        for (int i = tid; i < NTOT; i += 256) {
            int q4  = i & 7;
            int col = (i >> 3) % 18;
            int rem = i / (8*18);
            int row = rem % 10;
            int s   = rem / 10;
            int z  = d0 - 1 + s;
            int gh = h0 - 1 + row;
            int gw = w0 - 1 + col;
            float4 v = make_float4(0.f, 0.f, 0.f, 0.f);
            if (z >= 0 && z < DD && gh >= 0 && gh < HH && gw >= 0 && gw < WW)
                v = *(const float4*)(g_var + (((size_t)z*HH + gh)*WW + gw)*32 + q4*4);
            int pix = row*18 + col;
            int fo  = ((2*q4) ^ ((pix & 3) << 2)) << 1;   // float offset (mult of 4)
            *(float4*)(slab + s*SLICE + pix*32 + fo) = v;
        }
    }
    __syncthreads();

    float acc[DS][4];
    #pragma unroll
    for (int o = 0; o < DS; ++o)
        #pragma unroll
        for (int j = 0; j < 4; ++j) acc[o][j] = 0.f;

    unsigned afrag[2][NSL][4];
    const unsigned* slabu = (const unsigned*)slab;

    auto load_a = [&](unsigned (&dst)[NSL][4], int p_lo, int c) {
        const int fo = (((c*4 + tig) ^ ((p_lo & 3) << 2)) << 1);
        const unsigned* b = slabu + p_lo*32 + fo;
        #pragma unroll
        for (int s = 0; s < NSL; ++s) {
            uint2 lo = *(const uint2*)(b + s*SLICE);
            uint2 hi = *(const uint2*)(b + s*SLICE + 256);   // p_lo+8 pixels
            dst[s][0] = lo.x; dst[s][1] = hi.x;
            dst[s][2] = lo.y; dst[s][3] = hi.y;
        }
    };

    #pragma unroll 1
    for (int tap9 = 0; tap9 < 9; ++tap9) {
        const int kh = tap9 / 3, kw = tap9 - 3*kh;
        const int p_lo = (ty + kh)*18 + kw + gid;
        const unsigned* wb = (const unsigned*)s_w + tap9*256;

        load_a(afrag[0], p_lo, 0);
        #pragma unroll
        for (int c = 0; c < 4; ++c) {
            unsigned b[3][2];
            #pragma unroll
            for (int kd = 0; kd < 3; ++kd) {
                const unsigned* wp = wb + kd*9*256 + (c*8 + tig)*8 + gid;
                b[kd][0] = wp[0];
                b[kd][1] = wp[32];
            }
            if (c < 3) load_a(afrag[(c+1) & 1], p_lo, c+1);
            #pragma unroll
            for (int kd = 0; kd < 3; ++kd)
                #pragma unroll
                for (int o = 0; o < DS; ++o)
                    mma_tf32(acc[o], afrag[c & 1][o+kd], b[kd]);
        }
    }

    const float b0 = bias[2*tig], b1 = bias[2*tig+1];
    #pragma unroll
    for (int o = 0; o < DS; ++o) {
        int d = d0 + o;
        float* row = g_h0 + (((size_t)d*HH + (h0+ty))*WW + w0)*8;
        float2 v0 = make_float2(fmaxf(acc[o][0] + b0, 0.f), fmaxf(acc[o][1] + b1, 0.f));
        float2 v1 = make_float2(fmaxf(acc[o][2] + b0, 0.f), fmaxf(acc[o][3] + b1, 0.f));
        *(float2*)(row + gid*8     + 2*tig) = v0;
        *(float2*)(row + (gid+8)*8 + 2*tig) = v1;
    }
}

// ---------------------------------------------------------------------------
// Kernels 5-6: conv1 (8->8) / conv2 (8->1), tf32 mma, PS=8 unpadded,
// float2 fragment loads (k-index remap: k<4 -> cin 2k, else cin 2(k-4)+1).
// smem 53KB -> 3 blocks/SM.
// ---------------------------------------------------------------------------
template<int STAGE>
__global__ void __launch_bounds__(256, 3)
k_conv(const float* __restrict__ wgt, const float* __restrict__ bias) {
    constexpr int DS = 6, NSL = 8, PS = 8;
    constexpr int SLICE = 10*18*PS;               // 1440 floats

    const float* __restrict__ x   = (STAGE == 1) ? g_h0 : g_h1;
    float*       __restrict__ out = (STAGE == 1) ? g_h1 : g_cost;

    extern __shared__ float sm[];
    float* s_w  = sm;                             // [tap][k 8][co 8]
    float* slab = sm + 27*64;

    const int tid  = threadIdx.x;
    const int ty   = tid >> 5;
    const int lane = tid & 31;
    const int gid  = lane >> 2;
    const int tig  = lane & 3;
    const int w0 = blockIdx.x * 16;
    const int h0 = blockIdx.y * 8;
    const int d0 = blockIdx.z * DS;

    for (int i = tid; i < 27*64; i += 256) {
        int co  = i & 7;
        int k   = (i >> 3) & 7;
        int tap = i >> 6;
        int cin = (k < 4) ? 2*k : 2*(k-4) + 1;    // k-index remap
        float wv;
        if (STAGE == 1) wv = wgt[(co*8 + cin)*27 + tap];
        else            wv = (co == 0) ? wgt[cin*27 + tap] : 0.f;
        ((unsigned*)s_w)[i] = tf32cvt(wv);
    }
    {
        const int NTOT = NSL*10*18*2;             // float4 units
        for (int i = tid; i < NTOT; i += 256) {
            int g   = i & 1;
            int col = (i >> 1) % 18;
            int rem = i / 36;
            int row = rem % 10;
            int s   = rem / 10;
            int z  = d0 - 1 + s;
            int gh = h0 - 1 + row;
            int gw = w0 - 1 + col;
            float4 v = make_float4(0.f, 0.f, 0.f, 0.f);
            if (z >= 0 && z < DD && gh >= 0 && gh < HH && gw >= 0 && gw < WW)
                v = *(const float4*)(x + (((size_t)z*HH + gh)*WW + gw)*8 + g*4);
            uint4 u = make_uint4(tf32cvt(v.x), tf32cvt(v.y), tf32cvt(v.z), tf32cvt(v.w));
            *(uint4*)(slab + (s*180 + row*18 + col)*PS + g*4) = u;
        }
    }
    __syncthreads();

    float acc[DS][4];
    #pragma unroll
    for (int o = 0; o < DS; ++o)
        #pragma unroll
        for (int j = 0; j < 4; ++j) acc[o][j] = 0.f;

    const unsigned* slabu = (const unsigned*)slab;

    #pragma unroll 1
    for (int kh = 0; kh < 3; ++kh) {
        #pragma unroll 1
        for (int kw = 0; kw < 3; ++kw) {
            const int p_lo = (ty+kh)*18 + kw + gid;
            const unsigned* ab = slabu + p_lo*PS + tig*2;
            const unsigned* wb = (const unsigned*)s_w + (kh*3 + kw)*64;
            unsigned a[NSL][4];
            #pragma unroll
            for (int s = 0; s < NSL; ++s) {
                uint2 lo = *(const uint2*)(ab + s*SLICE);
                uint2 hi = *(const uint2*)(ab + s*SLICE + 8*PS);
                a[s][0] = lo.x; a[s][1] = hi.x;
                a[s][2] = lo.y; a[s][3] = hi.y;
            }
            unsigned b[3][2];
            #pragma unroll
            for (int kd = 0; kd < 3; ++kd) {
                const unsigned* wp = wb + kd*9*64 + tig*8 + gid;
                b[kd][0] = wp[0];
                b[kd][1] = wp[32];
            }
            #pragma unroll
            for (int kd = 0; kd < 3; ++kd)
                #pragma unroll
                for (int o = 0; o < DS; ++o)
                    mma_tf32(acc[o], a[o+kd], b[kd]);
        }
    }

    if (STAGE == 1) {
        const float b0 = bias[2*tig], b1 = bias[2*tig+1];
        #pragma unroll
        for (int o = 0; o < DS; ++o) {
            int d = d0 + o;
            float* row = out + (((size_t)d*HH + (h0+ty))*WW + w0)*8;
            float2 v0 = make_float2(fmaxf(acc[o][0] + b0, 0.f), fmaxf(acc[o][1] + b1, 0.f));
            float2 v1 = make_float2(fmaxf(acc[o][2] + b0, 0.f), fmaxf(acc[o][3] + b1, 0.f));
            *(float2*)(row + gid*8     + 2*tig) = v0;
            *(float2*)(row + (gid+8)*8 + 2*tig) = v1;
        }
    } else {
        const float b0 = bias[0];
        if (tig == 0) {
            #pragma unroll
            for (int o = 0; o < DS; ++o) {
                int d = d0 + o;
                float* row = out + ((size_t)d*HH + (h0+ty))*WW + w0;
                row[gid]   = acc[o][0] + b0;
                row[gid+8] = acc[o][2] + b0;
            }
        }
    }
}

// ---------------------------------------------------------------------------
// Kernel 7: softmax over D + expected depth + 4-tap confidence
// ---------------------------------------------------------------------------
__global__ void k_softmax(const float* __restrict__ dvals, float* __restrict__ out) {
    int p = blockIdx.x*blockDim.x + threadIdx.x;
    if (p >= HW) return;
    float c[DD];
    float m = -1e30f;
    #pragma unroll
    for (int d = 0; d < DD; ++d) { c[d] = g_cost[(size_t)d*HW + p]; m = fmaxf(m, c[d]); }
    float S = 0.f;
    #pragma unroll
    for (int d = 0; d < DD; ++d) { c[d] = expf(c[d] - m); S += c[d]; }
    float inv = 1.0f / S;
    float depth = 0.f, fid = 0.f;
    #pragma unroll
    for (int d = 0; d < DD; ++d) {
        float pr = c[d] * inv;
        depth = fmaf(pr, dvals[(size_t)d*HW + p], depth);
        fid   = fmaf(pr, (float)d, fid);
    }
    int di = (int)fid;
    di = max(0, min(DD-1, di));
    float conf = 0.f;
    #pragma unroll
    for (int d = 0; d < DD; ++d)
        if (d >= di-1 && d <= di+2) conf += c[d] * inv;
    out[p]      = depth;
    out[HW + p] = conf;
}

// ---------------------------------------------------------------------------
// Launch
// ---------------------------------------------------------------------------
extern "C" void kernel_launch(void* const* d_in, const int* in_sizes, int n_in,
                              void* d_out, int out_size) {
    const float* features = (const float*)d_in[0];
    const float* proj     = (const float*)d_in[1];
    const float* dvals    = (const float*)d_in[2];
    const float* w0 = (const float*)d_in[3];
    const float* b0 = (const float*)d_in[4];
    const float* w1 = (const float*)d_in[5];
    const float* b1 = (const float*)d_in[6];
    const float* w2 = (const float*)d_in[7];
    const float* b2 = (const float*)d_in[8];
    float* out = (float*)d_out;

    const int smem0  = (27*256 + 8*5760) * 4;    // 211968 B
    const int smem12 = (27*64  + 8*1440) * 4;    //  52992 B
    cudaFuncSetAttribute(k_conv0,   cudaFuncAttributeMaxDynamicSharedMemorySize, smem0);
    cudaFuncSetAttribute(k_conv<1>, cudaFuncAttributeMaxDynamicSharedMemorySize, smem12);
    cudaFuncSetAttribute(k_conv<2>, cudaFuncAttributeMaxDynamicSharedMemorySize, smem12);

    k_xform<<<1, 1>>>(proj);
    dim3 tgrid(HW/32, VV);
    k_transpose<<<tgrid, dim3(32, 8)>>>(features);
    k_warpvar<<<(DHW*8)/256, 256>>>(dvals);

    dim3 cgrid(WW/16, HH/8, DD/6);   // (10, 16, 8)
    k_conv0<<<cgrid, 256, smem0>>>(w0, b0);
    k_conv<1><<<cgrid, 256, smem12>>>(w1, b1);
    k_conv<2><<<cgrid, 256, smem12>>>(w2, b2);

    k_softmax<<<(HW + 255)/256, 256>>>(dvals, out);
}

// round 8
// speedup vs baseline: 1.1376x; 1.1376x over previous
#include <cuda_runtime.h>
#include <math.h>

#define VV 3
#define CC 32
#define DD 48
#define HH 128
#define WW 160
#define HW (HH*WW)        /* 20480 */
#define DHW (DD*HW)       /* 983040 */

// ---------------------------------------------------------------------------
// Scratch
// ---------------------------------------------------------------------------
__device__ float g_xform[2][12];
__device__ float g_feat_t[(size_t)VV*HW*CC];     // channels-last features
__device__ float g_var[(size_t)DHW*CC];          // variance, PAIR-PERMUTED + tf32
__device__ float g_h0[(size_t)DHW*8];            // conv0 out [D,H,W,8] plain
__device__ float g_h1[(size_t)DHW*8];            // conv1 out [D,H,W,8] plain
__device__ float g_cost[(size_t)DHW];            // conv2 out [D,H,W]
__device__ unsigned g_w0t[27*32*8];              // conv0 weights tf32 [tap][cin][co]

__device__ __forceinline__ unsigned tf32cvt(float f) {
    unsigned u;
    asm("cvt.rna.tf32.f32 %0, %1;" : "=r"(u) : "f"(f));
    return u;
}

// D(16x8) += A(16x8) * B(8x8), tf32 operands, f32 accum
__device__ __forceinline__ void mma_tf32(float* d, const unsigned* a, const unsigned* b) {
    asm("mma.sync.aligned.m16n8k8.row.col.f32.tf32.tf32.f32 "
        "{%0,%1,%2,%3}, {%4,%5,%6,%7}, {%8,%9}, {%0,%1,%2,%3};"
        : "+f"(d[0]), "+f"(d[1]), "+f"(d[2]), "+f"(d[3])
        : "r"(a[0]), "r"(a[1]), "r"(a[2]), "r"(a[3]), "r"(b[0]), "r"(b[1]));
}

// ---------------------------------------------------------------------------
// Kernel 1: projective transforms  M_v = C_v * inv(C_0)
// ---------------------------------------------------------------------------
__global__ void k_xform(const float* __restrict__ proj) {
    if (threadIdx.x || blockIdx.x) return;
    double Cm[3][4][4];
    for (int v = 0; v < 3; ++v) {
        double K[3][3], E[4][4];
        for (int i = 0; i < 3; ++i)
            for (int j = 0; j < 3; ++j)
                K[i][j] = (double)proj[((v*2+1)*4+i)*4+j];
        for (int i = 0; i < 4; ++i)
            for (int j = 0; j < 4; ++j)
                E[i][j] = (double)proj[((v*2+0)*4+i)*4+j];
        for (int i = 0; i < 3; ++i)
            for (int j = 0; j < 4; ++j) {
                double s = 0.0;
                for (int k = 0; k < 3; ++k) s += K[i][k]*E[k][j];
                Cm[v][i][j] = s;
            }
        for (int j = 0; j < 4; ++j) Cm[v][3][j] = E[3][j];
    }
    double A[4][8];
    for (int i = 0; i < 4; ++i)
        for (int j = 0; j < 4; ++j) { A[i][j] = Cm[0][i][j]; A[i][4+j] = (i==j) ? 1.0 : 0.0; }
    for (int col = 0; col < 4; ++col) {
        int piv = col;
        for (int r = col+1; r < 4; ++r) if (fabs(A[r][col]) > fabs(A[piv][col])) piv = r;
        if (piv != col)
            for (int j = 0; j < 8; ++j) { double t = A[col][j]; A[col][j] = A[piv][j]; A[piv][j] = t; }
        double iv = 1.0 / A[col][col];
        for (int j = 0; j < 8; ++j) A[col][j] *= iv;
        for (int r = 0; r < 4; ++r) if (r != col) {
            double f = A[r][col];
            for (int j = 0; j < 8; ++j) A[r][j] -= f * A[col][j];
        }
    }
    for (int v = 1; v < 3; ++v) {
        double M[3][4];
        for (int i = 0; i < 3; ++i)
            for (int j = 0; j < 4; ++j) {
                double s = 0.0;
                for (int k = 0; k < 4; ++k) s += Cm[v][i][k] * A[k][4+j];
                M[i][j] = s;
            }
        float* o = g_xform[v-1];
        o[0]=(float)M[0][0]; o[1]=(float)M[0][1]; o[2]=(float)M[0][2];
        o[3]=(float)M[1][0]; o[4]=(float)M[1][1]; o[5]=(float)M[1][2];
        o[6]=(float)M[2][0]; o[7]=(float)M[2][1]; o[8]=(float)M[2][2];
        o[9]=(float)M[0][3]; o[10]=(float)M[1][3]; o[11]=(float)M[2][3];
    }
}

// ---------------------------------------------------------------------------
// Kernel 1b: bake conv0 weights into tf32 [tap][cin][co] in gmem
// ---------------------------------------------------------------------------
__global__ void k_wprep(const float* __restrict__ w0) {
    int i = blockIdx.x*256 + threadIdx.x;
    if (i >= 27*256) return;
    int co  = i & 7;
    int cin = (i >> 3) & 31;
    int tap = i >> 8;
    g_w0t[i] = tf32cvt(w0[(co*32 + cin)*27 + tap]);
}

// ---------------------------------------------------------------------------
// Kernel 2: tiled transpose [V,C,H,W] -> [V,H,W,C]
// ---------------------------------------------------------------------------
__global__ void k_transpose(const float* __restrict__ f) {
    __shared__ float t[32][33];
    int v   = blockIdx.y;
    int hw0 = blockIdx.x * 32;
    for (int i = threadIdx.y; i < 32; i += 8)
        t[i][threadIdx.x] = f[((size_t)v*32 + i)*HW + hw0 + threadIdx.x];
    __syncthreads();
    for (int i = threadIdx.y; i < 32; i += 8)
        g_feat_t[((size_t)v*HW + hw0 + i)*32 + threadIdx.x] = t[threadIdx.x][i];
}

// ---------------------------------------------------------------------------
// Kernel 3: warp+variance. Output pair-permuted + tf32-pre-rounded.
// ---------------------------------------------------------------------------
__global__ void __launch_bounds__(256) k_warpvar(const float* __restrict__ dvals) {
    long long t = (long long)blockIdx.x*256 + threadIdx.x;
    int g   = (int)(t & 7);
    int idx = (int)(t >> 3);
    if (idx >= DHW) return;
    int w = idx % WW;
    int h = (idx / WW) % HH;
    float depth = dvals[idx];

    int   offs[2][4];
    float cwts[2][4];
    #pragma unroll
    for (int v = 0; v < 2; ++v) {
        const float* xf = g_xform[v];
        float x = (float)w, y = (float)h;
        float rx = xf[0]*x + xf[1]*y + xf[2];
        float ry = xf[3]*x + xf[4]*y + xf[5];
        float rz = xf[6]*x + xf[7]*y + xf[8];
        float px = rx*depth + xf[9];
        float py = ry*depth + xf[10];
        float pz = rz*depth + xf[11];
        float gx = px / pz / ((float)(WW-1)*0.5f) - 1.0f;
        float gy = py / pz / ((float)(HH-1)*0.5f) - 1.0f;
        float sx = (gx + 1.0f) * 0.5f * (float)(WW-1);
        float sy = (gy + 1.0f) * 0.5f * (float)(HH-1);
        float x0 = floorf(sx), y0 = floorf(sy);
        float wx1 = sx - x0, wx0 = 1.0f - wx1;
        float wy1 = sy - y0, wy0 = 1.0f - wy1;
        float cx[2] = {x0, x0+1.0f}, cy[2] = {y0, y0+1.0f};
        float wx[2] = {wx0, wx1}, wy[2] = {wy0, wy1};
        #pragma unroll
        for (int cyi = 0; cyi < 2; ++cyi)
        #pragma unroll
        for (int cxi = 0; cxi < 2; ++cxi) {
            float xi = cx[cxi], yi = cy[cyi];
            bool valid = (xi >= 0.0f) && (xi <= (float)(WW-1)) &&
                         (yi >= 0.0f) && (yi <= (float)(HH-1));
            float xc = fminf(fmaxf(xi, 0.0f), (float)(WW-1));
            float yc = fminf(fmaxf(yi, 0.0f), (float)(HH-1));
            int ii = (int)yc * WW + (int)xc;
            offs[v][cyi*2+cxi] = ii * CC + g*4;
            cwts[v][cyi*2+cxi] = wx[cxi]*wy[cyi] * (valid ? 1.0f : 0.0f);
        }
    }

    float4 r = *(const float4*)(g_feat_t + (size_t)(h*WW + w)*CC + g*4);
    const float* s1 = g_feat_t + (size_t)HW*CC;
    const float* s2 = g_feat_t + (size_t)2*HW*CC;

    float sx_ = r.x, sy_ = r.y, sz_ = r.z, sw_ = r.w;
    float qx = r.x*r.x, qy = r.y*r.y, qz = r.z*r.z, qw = r.w*r.w;
    #pragma unroll
    for (int v = 0; v < 2; ++v) {
        const float* base = (v == 0) ? s1 : s2;
        float wxp = 0.f, wyp = 0.f, wzp = 0.f, wwp = 0.f;
        #pragma unroll
        for (int k = 0; k < 4; ++k) {
            float cw = cwts[v][k];
            const float4 f = *(const float4*)(base + offs[v][k]);
            wxp = fmaf(cw, f.x, wxp);
            wyp = fmaf(cw, f.y, wyp);
            wzp = fmaf(cw, f.z, wzp);
            wwp = fmaf(cw, f.w, wwp);
        }
        sx_ += wxp; sy_ += wyp; sz_ += wzp; sw_ += wwp;
        qx = fmaf(wxp, wxp, qx); qy = fmaf(wyp, wyp, qy);
        qz = fmaf(wzp, wzp, qz); qw = fmaf(wwp, wwp, qw);
    }
    float vals[4];
    float mx = sx_ / 3.0f, my = sy_ / 3.0f, mz = sz_ / 3.0f, mw = sw_ / 3.0f;
    vals[0] = qx / 3.0f - mx*mx;
    vals[1] = qy / 3.0f - my*my;
    vals[2] = qz / 3.0f - mz*mz;
    vals[3] = qw / 3.0f - mw*mw;
    float* outb = g_var + (size_t)idx*CC + (g >> 1)*8 + (g & 1);
    #pragma unroll
    for (int j = 0; j < 4; ++j)
        outb[2*j] = __uint_as_float(tf32cvt(vals[j]));
}

// ---------------------------------------------------------------------------
// Kernel 4: conv0 (32->8) tf32 mma. DS=2, NSL=4 slab (92KB) -> 2 CTAs/SM,
// B-fragments straight from gmem (g_w0t, L1/L2-resident), pair-permuted slab.
// ---------------------------------------------------------------------------
__global__ void __launch_bounds__(256, 2)
k_conv0(const float* __restrict__ wgt, const float* __restrict__ bias) {
    constexpr int DS = 2, NSL = 4;
    constexpr int SLICE = 10*18*32;               // 5760 floats

    extern __shared__ float sm[];
    float* slab = sm;                             // 4 slices, 92160 B

    const int tid  = threadIdx.x;
    const int ty   = tid >> 5;                    // warp id = h row 0..7
    const int lane = tid & 31;
    const int gid  = lane >> 2;
    const int tig  = lane & 3;
    const int w0 = blockIdx.x * 16;
    const int h0 = blockIdx.y * 8;
    const int d0 = blockIdx.z * DS;

    // slab fill: g_var already tf32 + pair-permuted; swizzled pair position.
    {
        const int NTOT = NSL*10*18*8;             // float4 units
        for (int i = tid; i < NTOT; i += 256) {
            int q4  = i & 7;
            int col = (i >> 3) % 18;
            int rem = i / (8*18);
            int row = rem % 10;
            int s   = rem / 10;
            int z  = d0 - 1 + s;
            int gh = h0 - 1 + row;
            int gw = w0 - 1 + col;
            float4 v = make_float4(0.f, 0.f, 0.f, 0.f);
            if (z >= 0 && z < DD && gh >= 0 && gh < HH && gw >= 0 && gw < WW)
                v = *(const float4*)(g_var + (((size_t)z*HH + gh)*WW + gw)*32 + q4*4);
            int pix = row*18 + col;
            int fo  = ((2*q4) ^ ((pix & 3) << 2)) << 1;
            *(float4*)(slab + s*SLICE + pix*32 + fo) = v;
        }
    }
    __syncthreads();

    float acc[DS][4];
    #pragma unroll
    for (int o = 0; o < DS; ++o)
        #pragma unroll
        for (int j = 0; j < 4; ++j) acc[o][j] = 0.f;

    const unsigned* slabu = (const unsigned*)slab;

    #pragma unroll 1
    for (int kh = 0; kh < 3; ++kh) {
        #pragma unroll
        for (int kw = 0; kw < 3; ++kw) {
            const int tap9 = kh*3 + kw;
            const int p_lo = (ty + kh)*18 + kw + gid;
            const int rot  = (p_lo & 3) << 2;
            #pragma unroll
            for (int c = 0; c < 4; ++c) {
                const int fo = ((c*4 + tig) ^ rot) << 1;
                const unsigned* ab = slabu + p_lo*32 + fo;
                unsigned a[NSL][4];
                #pragma unroll
                for (int s = 0; s < NSL; ++s) {
                    uint2 lo = *(const uint2*)(ab + s*SLICE);
                    uint2 hi = *(const uint2*)(ab + s*SLICE + 256);
                    a[s][0] = lo.x; a[s][1] = hi.x;
                    a[s][2] = lo.y; a[s][3] = hi.y;
                }
                unsigned b[3][2];
                #pragma unroll
                for (int kd = 0; kd < 3; ++kd) {
                    const unsigned* wp = g_w0t + (kd*9 + tap9)*256 + (c*8 + tig)*8 + gid;
                    b[kd][0] = wp[0];
                    b[kd][1] = wp[32];
                }
                #pragma unroll
                for (int kd = 0; kd < 3; ++kd)
                    #pragma unroll
                    for (int o = 0; o < DS; ++o)
                        mma_tf32(acc[o], a[o+kd], b[kd]);
            }
        }
    }

    const float b0 = bias[2*tig], b1 = bias[2*tig+1];
    #pragma unroll
    for (int o = 0; o < DS; ++o) {
        int d = d0 + o;
        float* row = g_h0 + (((size_t)d*HH + (h0+ty))*WW + w0)*8;
        float2 v0 = make_float2(fmaxf(acc[o][0] + b0, 0.f), fmaxf(acc[o][1] + b1, 0.f));
        float2 v1 = make_float2(fmaxf(acc[o][2] + b0, 0.f), fmaxf(acc[o][3] + b1, 0.f));
        *(float2*)(row + gid*8     + 2*tig) = v0;
        *(float2*)(row + (gid+8)*8 + 2*tig) = v1;
    }
}

// ---------------------------------------------------------------------------
// Kernels 5-6: conv1 (8->8) / conv2 (8->1), tf32 mma, PS=8 unpadded,
// float2 fragment loads (k remap: k<4 -> cin 2k, else 2(k-4)+1). 3 blocks/SM.
// ---------------------------------------------------------------------------
template<int STAGE>
__global__ void __launch_bounds__(256, 3)
k_conv(const float* __restrict__ wgt, const float* __restrict__ bias) {
    constexpr int DS = 6, NSL = 8, PS = 8;
    constexpr int SLICE = 10*18*PS;               // 1440 floats

    const float* __restrict__ x   = (STAGE == 1) ? g_h0 : g_h1;
    float*       __restrict__ out = (STAGE == 1) ? g_h1 : g_cost;

    extern __shared__ float sm[];
    float* s_w  = sm;                             // [tap][k 8][co 8]
    float* slab = sm + 27*64;

    const int tid  = threadIdx.x;
    const int ty   = tid >> 5;
    const int lane = tid & 31;
    const int gid  = lane >> 2;
    const int tig  = lane & 3;
    const int w0 = blockIdx.x * 16;
    const int h0 = blockIdx.y * 8;
    const int d0 = blockIdx.z * DS;

    for (int i = tid; i < 27*64; i += 256) {
        int co  = i & 7;
        int k   = (i >> 3) & 7;
        int tap = i >> 6;
        int cin = (k < 4) ? 2*k : 2*(k-4) + 1;
        float wv;
        if (STAGE == 1) wv = wgt[(co*8 + cin)*27 + tap];
        else            wv = (co == 0) ? wgt[cin*27 + tap] : 0.f;
        ((unsigned*)s_w)[i] = tf32cvt(wv);
    }
    {
        const int NTOT = NSL*10*18*2;
        for (int i = tid; i < NTOT; i += 256) {
            int g   = i & 1;
            int col = (i >> 1) % 18;
            int rem = i / 36;
            int row = rem % 10;
            int s   = rem / 10;
            int z  = d0 - 1 + s;
            int gh = h0 - 1 + row;
            int gw = w0 - 1 + col;
            float4 v = make_float4(0.f, 0.f, 0.f, 0.f);
            if (z >= 0 && z < DD && gh >= 0 && gh < HH && gw >= 0 && gw < WW)
                v = *(const float4*)(x + (((size_t)z*HH + gh)*WW + gw)*8 + g*4);
            uint4 u = make_uint4(tf32cvt(v.x), tf32cvt(v.y), tf32cvt(v.z), tf32cvt(v.w));
            *(uint4*)(slab + (s*180 + row*18 + col)*PS + g*4) = u;
        }
    }
    __syncthreads();

    float acc[DS][4];
    #pragma unroll
    for (int o = 0; o < DS; ++o)
        #pragma unroll
        for (int j = 0; j < 4; ++j) acc[o][j] = 0.f;

    const unsigned* slabu = (const unsigned*)slab;

    #pragma unroll 1
    for (int kh = 0; kh < 3; ++kh) {
        #pragma unroll
        for (int kw = 0; kw < 3; ++kw) {
            const int p_lo = (ty+kh)*18 + kw + gid;
            const unsigned* ab = slabu + p_lo*PS + tig*2;
            const unsigned* wb = (const unsigned*)s_w + (kh*3 + kw)*64;
            unsigned a[NSL][4];
            #pragma unroll
            for (int s = 0; s < NSL; ++s) {
                uint2 lo = *(const uint2*)(ab + s*SLICE);
                uint2 hi = *(const uint2*)(ab + s*SLICE + 8*PS);
                a[s][0] = lo.x; a[s][1] = hi.x;
                a[s][2] = lo.y; a[s][3] = hi.y;
            }
            unsigned b[3][2];
            #pragma unroll
            for (int kd = 0; kd < 3; ++kd) {
                const unsigned* wp = wb + kd*9*64 + tig*8 + gid;
                b[kd][0] = wp[0];
                b[kd][1] = wp[32];
            }
            #pragma unroll
            for (int kd = 0; kd < 3; ++kd)
                #pragma unroll
                for (int o = 0; o < DS; ++o)
                    mma_tf32(acc[o], a[o+kd], b[kd]);
        }
    }

    if (STAGE == 1) {
        const float b0 = bias[2*tig], b1 = bias[2*tig+1];
        #pragma unroll
        for (int o = 0; o < DS; ++o) {
            int d = d0 + o;
            float* row = out + (((size_t)d*HH + (h0+ty))*WW + w0)*8;
            float2 v0 = make_float2(fmaxf(acc[o][0] + b0, 0.f), fmaxf(acc[o][1] + b1, 0.f));
            float2 v1 = make_float2(fmaxf(acc[o][2] + b0, 0.f), fmaxf(acc[o][3] + b1, 0.f));
            *(float2*)(row + gid*8     + 2*tig) = v0;
            *(float2*)(row + (gid+8)*8 + 2*tig) = v1;
        }
    } else {
        const float b0 = bias[0];
        if (tig == 0) {
            #pragma unroll
            for (int o = 0; o < DS; ++o) {
                int d = d0 + o;
                float* row = out + ((size_t)d*HH + (h0+ty))*WW + w0;
                row[gid]   = acc[o][0] + b0;
                row[gid+8] = acc[o][2] + b0;
            }
        }
    }
}

// ---------------------------------------------------------------------------
// Kernel 7: softmax over D + expected depth + 4-tap confidence
// ---------------------------------------------------------------------------
__global__ void k_softmax(const float* __restrict__ dvals, float* __restrict__ out) {
    int p = blockIdx.x*blockDim.x + threadIdx.x;
    if (p >= HW) return;
    float c[DD];
    float m = -1e30f;
    #pragma unroll
    for (int d = 0; d < DD; ++d) { c[d] = g_cost[(size_t)d*HW + p]; m = fmaxf(m, c[d]); }
    float S = 0.f;
    #pragma unroll
    for (int d = 0; d < DD; ++d) { c[d] = expf(c[d] - m); S += c[d]; }
    float inv = 1.0f / S;
    float depth = 0.f, fid = 0.f;
    #pragma unroll
    for (int d = 0; d < DD; ++d) {
        float pr = c[d] * inv;
        depth = fmaf(pr, dvals[(size_t)d*HW + p], depth);
        fid   = fmaf(pr, (float)d, fid);
    }
    int di = (int)fid;
    di = max(0, min(DD-1, di));
    float conf = 0.f;
    #pragma unroll
    for (int d = 0; d < DD; ++d)
        if (d >= di-1 && d <= di+2) conf += c[d] * inv;
    out[p]      = depth;
    out[HW + p] = conf;
}

// ---------------------------------------------------------------------------
// Launch
// ---------------------------------------------------------------------------
extern "C" void kernel_launch(void* const* d_in, const int* in_sizes, int n_in,
                              void* d_out, int out_size) {
    const float* features = (const float*)d_in[0];
    const float* proj     = (const float*)d_in[1];
    const float* dvals    = (const float*)d_in[2];
    const float* w0 = (const float*)d_in[3];
    const float* b0 = (const float*)d_in[4];
    const float* w1 = (const float*)d_in[5];
    const float* b1 = (const float*)d_in[6];
    const float* w2 = (const float*)d_in[7];
    const float* b2 = (const float*)d_in[8];
    float* out = (float*)d_out;

    const int smem0  = 4*5760*4;                 //  92160 B (slab only)
    const int smem12 = (27*64 + 8*1440) * 4;     //  52992 B
    cudaFuncSetAttribute(k_conv0,   cudaFuncAttributeMaxDynamicSharedMemorySize, smem0);
    cudaFuncSetAttribute(k_conv<1>, cudaFuncAttributeMaxDynamicSharedMemorySize, smem12);
    cudaFuncSetAttribute(k_conv<2>, cudaFuncAttributeMaxDynamicSharedMemorySize, smem12);

    k_xform<<<1, 1>>>(proj);
    k_wprep<<<27, 256>>>(w0);
    dim3 tgrid(HW/32, VV);
    k_transpose<<<tgrid, dim3(32, 8)>>>(features);
    k_warpvar<<<(DHW*8)/256, 256>>>(dvals);

    dim3 cgrid0(WW/16, HH/8, DD/2);   // (10, 16, 24)
    dim3 cgrid12(WW/16, HH/8, DD/6);  // (10, 16, 8)
    k_conv0<<<cgrid0, 256, smem0>>>(w0, b0);
    k_conv<1><<<cgrid12, 256, smem12>>>(w1, b1);
    k_conv<2><<<cgrid12, 256, smem12>>>(w2, b2);

    k_softmax<<<(HW + 255)/256, 256>>>(dvals, out);
}

// round 9
// speedup vs baseline: 1.2730x; 1.1190x over previous
#include <cuda_runtime.h>
#include <math.h>

#define VV 3
#define CC 32
#define DD 48
#define HH 128
#define WW 160
#define HW (HH*WW)        /* 20480 */
#define DHW (DD*HW)       /* 983040 */

// ---------------------------------------------------------------------------
// Scratch
// ---------------------------------------------------------------------------
__device__ float g_xform[2][12];
__device__ float g_feat_t[(size_t)VV*HW*CC];     // channels-last features
__device__ float g_var[(size_t)DHW*CC];          // variance, PAIR-PERMUTED + tf32
__device__ float g_h0[(size_t)DHW*8];            // conv0 out [D,H,W,8] plain
__device__ float g_h1[(size_t)DHW*8];            // conv1 out [D,H,W,8] plain
__device__ float g_cost[(size_t)DHW];            // conv2 out [D,H,W]
__device__ unsigned g_w0t[27*32*8];              // conv0 weights tf32 [tap][cin][co]

__device__ __forceinline__ unsigned tf32cvt(float f) {
    unsigned u;
    asm("cvt.rna.tf32.f32 %0, %1;" : "=r"(u) : "f"(f));
    return u;
}

// D(16x8) += A(16x8) * B(8x8), tf32 operands, f32 accum
__device__ __forceinline__ void mma_tf32(float* d, const unsigned* a, const unsigned* b) {
    asm("mma.sync.aligned.m16n8k8.row.col.f32.tf32.tf32.f32 "
        "{%0,%1,%2,%3}, {%4,%5,%6,%7}, {%8,%9}, {%0,%1,%2,%3};"
        : "+f"(d[0]), "+f"(d[1]), "+f"(d[2]), "+f"(d[3])
        : "r"(a[0]), "r"(a[1]), "r"(a[2]), "r"(a[3]), "r"(b[0]), "r"(b[1]));
}

// ---------------------------------------------------------------------------
// Kernel 1: projective transforms  M_v = C_v * inv(C_0)
// ---------------------------------------------------------------------------
__global__ void k_xform(const float* __restrict__ proj) {
    if (threadIdx.x || blockIdx.x) return;
    double Cm[3][4][4];
    for (int v = 0; v < 3; ++v) {
        double K[3][3], E[4][4];
        for (int i = 0; i < 3; ++i)
            for (int j = 0; j < 3; ++j)
                K[i][j] = (double)proj[((v*2+1)*4+i)*4+j];
        for (int i = 0; i < 4; ++i)
            for (int j = 0; j < 4; ++j)
                E[i][j] = (double)proj[((v*2+0)*4+i)*4+j];
        for (int i = 0; i < 3; ++i)
            for (int j = 0; j < 4; ++j) {
                double s = 0.0;
                for (int k = 0; k < 3; ++k) s += K[i][k]*E[k][j];
                Cm[v][i][j] = s;
            }
        for (int j = 0; j < 4; ++j) Cm[v][3][j] = E[3][j];
    }
    double A[4][8];
    for (int i = 0; i < 4; ++i)
        for (int j = 0; j < 4; ++j) { A[i][j] = Cm[0][i][j]; A[i][4+j] = (i==j) ? 1.0 : 0.0; }
    for (int col = 0; col < 4; ++col) {
        int piv = col;
        for (int r = col+1; r < 4; ++r) if (fabs(A[r][col]) > fabs(A[piv][col])) piv = r;
        if (piv != col)
            for (int j = 0; j < 8; ++j) { double t = A[col][j]; A[col][j] = A[piv][j]; A[piv][j] = t; }
        double iv = 1.0 / A[col][col];
        for (int j = 0; j < 8; ++j) A[col][j] *= iv;
        for (int r = 0; r < 4; ++r) if (r != col) {
            double f = A[r][col];
            for (int j = 0; j < 8; ++j) A[r][j] -= f * A[col][j];
        }
    }
    for (int v = 1; v < 3; ++v) {
        double M[3][4];
        for (int i = 0; i < 3; ++i)
            for (int j = 0; j < 4; ++j) {
                double s = 0.0;
                for (int k = 0; k < 4; ++k) s += Cm[v][i][k] * A[k][4+j];
                M[i][j] = s;
            }
        float* o = g_xform[v-1];
        o[0]=(float)M[0][0]; o[1]=(float)M[0][1]; o[2]=(float)M[0][2];
        o[3]=(float)M[1][0]; o[4]=(float)M[1][1]; o[5]=(float)M[1][2];
        o[6]=(float)M[2][0]; o[7]=(float)M[2][1]; o[8]=(float)M[2][2];
        o[9]=(float)M[0][3]; o[10]=(float)M[1][3]; o[11]=(float)M[2][3];
    }
}

// ---------------------------------------------------------------------------
// Kernel 1b: bake conv0 weights into tf32 [tap][cin][co] in gmem
// ---------------------------------------------------------------------------
__global__ void k_wprep(const float* __restrict__ w0) {
    int i = blockIdx.x*256 + threadIdx.x;
    if (i >= 27*256) return;
    int co  = i & 7;
    int cin = (i >> 3) & 31;
    int tap = i >> 8;
    g_w0t[i] = tf32cvt(w0[(co*32 + cin)*27 + tap]);
}

// ---------------------------------------------------------------------------
// Kernel 2: tiled transpose [V,C,H,W] -> [V,H,W,C]
// ---------------------------------------------------------------------------
__global__ void k_transpose(const float* __restrict__ f) {
    __shared__ float t[32][33];
    int v   = blockIdx.y;
    int hw0 = blockIdx.x * 32;
    for (int i = threadIdx.y; i < 32; i += 8)
        t[i][threadIdx.x] = f[((size_t)v*32 + i)*HW + hw0 + threadIdx.x];
    __syncthreads();
    for (int i = threadIdx.y; i < 32; i += 8)
        g_feat_t[((size_t)v*HW + hw0 + i)*32 + threadIdx.x] = t[threadIdx.x][i];
}

// ---------------------------------------------------------------------------
// Kernel 3: warp+variance, two-phase.
// Phase 1: 1 thread/voxel computes corner (offset,weight) metadata -> smem.
// Phase 2: 8 lanes/voxel gather (1 line per corner) + variance + permuted write.
// ---------------------------------------------------------------------------
__global__ void __launch_bounds__(256) k_warpvar(const float* __restrict__ dvals) {
    __shared__ float2 s_ow[256*9];   // per voxel: 8 (offset,weight) + (refoff, -)

    const int tid  = threadIdx.x;
    const int vox0 = blockIdx.x * 256;

    // ---- Phase 1: metadata (1 thread = 1 voxel) ----
    {
        int idx = vox0 + tid;
        int w = idx % WW;
        int h = (idx / WW) % HH;
        float depth = dvals[idx];

        #pragma unroll
        for (int v = 0; v < 2; ++v) {
            const float* xf = g_xform[v];
            float x = (float)w, y = (float)h;
            float rx = xf[0]*x + xf[1]*y + xf[2];
            float ry = xf[3]*x + xf[4]*y + xf[5];
            float rz = xf[6]*x + xf[7]*y + xf[8];
            float px = rx*depth + xf[9];
            float py = ry*depth + xf[10];
            float pz = rz*depth + xf[11];
            float gx = px / pz / ((float)(WW-1)*0.5f) - 1.0f;
            float gy = py / pz / ((float)(HH-1)*0.5f) - 1.0f;
            float sx = (gx + 1.0f) * 0.5f * (float)(WW-1);
            float sy = (gy + 1.0f) * 0.5f * (float)(HH-1);
            float x0 = floorf(sx), y0 = floorf(sy);
            float wx1 = sx - x0, wx0 = 1.0f - wx1;
            float wy1 = sy - y0, wy0 = 1.0f - wy1;
            float cx[2] = {x0, x0+1.0f}, cy[2] = {y0, y0+1.0f};
            float wx[2] = {wx0, wx1}, wy[2] = {wy0, wy1};
            #pragma unroll
            for (int cyi = 0; cyi < 2; ++cyi)
            #pragma unroll
            for (int cxi = 0; cxi < 2; ++cxi) {
                float xi = cx[cxi], yi = cy[cyi];
                bool valid = (xi >= 0.0f) && (xi <= (float)(WW-1)) &&
                             (yi >= 0.0f) && (yi <= (float)(HH-1));
                float xc = fminf(fmaxf(xi, 0.0f), (float)(WW-1));
                float yc = fminf(fmaxf(yi, 0.0f), (float)(HH-1));
                int ii = (int)yc * WW + (int)xc;
                float wgt = wx[cxi]*wy[cyi] * (valid ? 1.0f : 0.0f);
                s_ow[tid*9 + v*4 + cyi*2 + cxi] =
                    make_float2(__int_as_float(ii * CC), wgt);
            }
        }
        s_ow[tid*9 + 8] = make_float2(__int_as_float((h*WW + w)*CC), 0.f);
    }
    __syncthreads();

    // ---- Phase 2: gathers (8 lanes per voxel, 8 passes) ----
    const int g    = tid & 7;
    const int slot = tid >> 3;
    const float* s1 = g_feat_t + (size_t)HW*CC;
    const float* s2 = g_feat_t + (size_t)2*HW*CC;

    #pragma unroll 1
    for (int pass = 0; pass < 8; ++pass) {
        int j   = pass*32 + slot;
        int idx = vox0 + j;
        const float2* mw = s_ow + j*9;

        int refo = __float_as_int(mw[8].x);
        float4 r = *(const float4*)(g_feat_t + refo + g*4);

        float sx_ = r.x, sy_ = r.y, sz_ = r.z, sw_ = r.w;
        float qx = r.x*r.x, qy = r.y*r.y, qz = r.z*r.z, qw = r.w*r.w;
        #pragma unroll
        for (int v = 0; v < 2; ++v) {
            const float* base = (v == 0) ? s1 : s2;
            float wxp = 0.f, wyp = 0.f, wzp = 0.f, wwp = 0.f;
            #pragma unroll
            for (int k = 0; k < 4; ++k) {
                float2 ow = mw[v*4 + k];
                float cw = ow.y;
                const float4 f = *(const float4*)(base + __float_as_int(ow.x) + g*4);
                wxp = fmaf(cw, f.x, wxp);
                wyp = fmaf(cw, f.y, wyp);
                wzp = fmaf(cw, f.z, wzp);
                wwp = fmaf(cw, f.w, wwp);
            }
            sx_ += wxp; sy_ += wyp; sz_ += wzp; sw_ += wwp;
            qx = fmaf(wxp, wxp, qx); qy = fmaf(wyp, wyp, qy);
            qz = fmaf(wzp, wzp, qz); qw = fmaf(wwp, wwp, qw);
        }
        float vals[4];
        float mx = sx_ / 3.0f, my = sy_ / 3.0f, mz = sz_ / 3.0f, mw2 = sw_ / 3.0f;
        vals[0] = qx / 3.0f - mx*mx;
        vals[1] = qy / 3.0f - my*my;
        vals[2] = qz / 3.0f - mz*mz;
        vals[3] = qw / 3.0f - mw2*mw2;
        float* outb = g_var + (size_t)idx*CC + (g >> 1)*8 + (g & 1);
        #pragma unroll
        for (int jj = 0; jj < 4; ++jj)
            outb[2*jj] = __uint_as_float(tf32cvt(vals[jj]));
    }
}

// ---------------------------------------------------------------------------
// Kernel 4: conv0 (32->8) tf32 mma. DS=2, NSL=4 slab (92KB) -> 2 CTAs/SM,
// B-fragments straight from gmem (g_w0t, L1/L2-resident), pair-permuted slab.
// ---------------------------------------------------------------------------
__global__ void __launch_bounds__(256, 2)
k_conv0(const float* __restrict__ wgt, const float* __restrict__ bias) {
    constexpr int DS = 2, NSL = 4;
    constexpr int SLICE = 10*18*32;               // 5760 floats

    extern __shared__ float sm[];
    float* slab = sm;                             // 4 slices, 92160 B

    const int tid  = threadIdx.x;
    const int ty   = tid >> 5;                    // warp id = h row 0..7
    const int lane = tid & 31;
    const int gid  = lane >> 2;
    const int tig  = lane & 3;
    const int w0 = blockIdx.x * 16;
    const int h0 = blockIdx.y * 8;
    const int d0 = blockIdx.z * DS;

    {
        const int NTOT = NSL*10*18*8;             // float4 units
        for (int i = tid; i < NTOT; i += 256) {
            int q4  = i & 7;
            int col = (i >> 3) % 18;
            int rem = i / (8*18);
            int row = rem % 10;
            int s   = rem / 10;
            int z  = d0 - 1 + s;
            int gh = h0 - 1 + row;
            int gw = w0 - 1 + col;
            float4 v = make_float4(0.f, 0.f, 0.f, 0.f);
            if (z >= 0 && z < DD && gh >= 0 && gh < HH && gw >= 0 && gw < WW)
                v = *(const float4*)(g_var + (((size_t)z*HH + gh)*WW + gw)*32 + q4*4);
            int pix = row*18 + col;
            int fo  = ((2*q4) ^ ((pix & 3) << 2)) << 1;
            *(float4*)(slab + s*SLICE + pix*32 + fo) = v;
        }
    }
    __syncthreads();

    float acc[DS][4];
    #pragma unroll
    for (int o = 0; o < DS; ++o)
        #pragma unroll
        for (int j = 0; j < 4; ++j) acc[o][j] = 0.f;

    const unsigned* slabu = (const unsigned*)slab;

    #pragma unroll 1
    for (int kh = 0; kh < 3; ++kh) {
        #pragma unroll
        for (int kw = 0; kw < 3; ++kw) {
            const int tap9 = kh*3 + kw;
            const int p_lo = (ty + kh)*18 + kw + gid;
            const int rot  = (p_lo & 3) << 2;
            #pragma unroll
            for (int c = 0; c < 4; ++c) {
                const int fo = ((c*4 + tig) ^ rot) << 1;
                const unsigned* ab = slabu + p_lo*32 + fo;
                unsigned a[NSL][4];
                #pragma unroll
                for (int s = 0; s < NSL; ++s) {
                    uint2 lo = *(const uint2*)(ab + s*SLICE);
                    uint2 hi = *(const uint2*)(ab + s*SLICE + 256);
                    a[s][0] = lo.x; a[s][1] = hi.x;
                    a[s][2] = lo.y; a[s][3] = hi.y;
                }
                unsigned b[3][2];
                #pragma unroll
                for (int kd = 0; kd < 3; ++kd) {
                    const unsigned* wp = g_w0t + (kd*9 + tap9)*256 + (c*8 + tig)*8 + gid;
                    b[kd][0] = wp[0];
                    b[kd][1] = wp[32];
                }
                #pragma unroll
                for (int kd = 0; kd < 3; ++kd)
                    #pragma unroll
                    for (int o = 0; o < DS; ++o)
                        mma_tf32(acc[o], a[o+kd], b[kd]);
            }
        }
    }

    const float b0 = bias[2*tig], b1 = bias[2*tig+1];
    #pragma unroll
    for (int o = 0; o < DS; ++o) {
        int d = d0 + o;
        float* row = g_h0 + (((size_t)d*HH + (h0+ty))*WW + w0)*8;
        float2 v0 = make_float2(fmaxf(acc[o][0] + b0, 0.f), fmaxf(acc[o][1] + b1, 0.f));
        float2 v1 = make_float2(fmaxf(acc[o][2] + b0, 0.f), fmaxf(acc[o][3] + b1, 0.f));
        *(float2*)(row + gid*8     + 2*tig) = v0;
        *(float2*)(row + (gid+8)*8 + 2*tig) = v1;
    }
}

// ---------------------------------------------------------------------------
// Kernels 5-6: conv1 (8->8) / conv2 (8->1), tf32 mma, PS=8 unpadded,
// float2 fragment loads (k remap: k<4 -> cin 2k, else 2(k-4)+1). 3 blocks/SM.
// ---------------------------------------------------------------------------
template<int STAGE>
__global__ void __launch_bounds__(256, 3)
k_conv(const float* __restrict__ wgt, const float* __restrict__ bias) {
    constexpr int DS = 6, NSL = 8, PS = 8;
    constexpr int SLICE = 10*18*PS;               // 1440 floats

    const float* __restrict__ x   = (STAGE == 1) ? g_h0 : g_h1;
    float*       __restrict__ out = (STAGE == 1) ? g_h1 : g_cost;

    extern __shared__ float sm[];
    float* s_w  = sm;                             // [tap][k 8][co 8]
    float* slab = sm + 27*64;

    const int tid  = threadIdx.x;
    const int ty   = tid >> 5;
    const int lane = tid & 31;
    const int gid  = lane >> 2;
    const int tig  = lane & 3;
    const int w0 = blockIdx.x * 16;
    const int h0 = blockIdx.y * 8;
    const int d0 = blockIdx.z * DS;

    for (int i = tid; i < 27*64; i += 256) {
        int co  = i & 7;
        int k   = (i >> 3) & 7;
        int tap = i >> 6;
        int cin = (k < 4) ? 2*k : 2*(k-4) + 1;
        float wv;
        if (STAGE == 1) wv = wgt[(co*8 + cin)*27 + tap];
        else            wv = (co == 0) ? wgt[cin*27 + tap] : 0.f;
        ((unsigned*)s_w)[i] = tf32cvt(wv);
    }
    {
        const int NTOT = NSL*10*18*2;
        for (int i = tid; i < NTOT; i += 256) {
            int g   = i & 1;
            int col = (i >> 1) % 18;
            int rem = i / 36;
            int row = rem % 10;
            int s   = rem / 10;
            int z  = d0 - 1 + s;
            int gh = h0 - 1 + row;
            int gw = w0 - 1 + col;
            float4 v = make_float4(0.f, 0.f, 0.f, 0.f);
            if (z >= 0 && z < DD && gh >= 0 && gh < HH && gw >= 0 && gw < WW)
                v = *(const float4*)(x + (((size_t)z*HH + gh)*WW + gw)*8 + g*4);
            uint4 u = make_uint4(tf32cvt(v.x), tf32cvt(v.y), tf32cvt(v.z), tf32cvt(v.w));
            *(uint4*)(slab + (s*180 + row*18 + col)*PS + g*4) = u;
        }
    }
    __syncthreads();

    float acc[DS][4];
    #pragma unroll
    for (int o = 0; o < DS; ++o)
        #pragma unroll
        for (int j = 0; j < 4; ++j) acc[o][j] = 0.f;

    const unsigned* slabu = (const unsigned*)slab;

    #pragma unroll 1
    for (int kh = 0; kh < 3; ++kh) {
        #pragma unroll
        for (int kw = 0; kw < 3; ++kw) {
            const int p_lo = (ty+kh)*18 + kw + gid;
            const unsigned* ab = slabu + p_lo*PS + tig*2;
            const unsigned* wb = (const unsigned*)s_w + (kh*3 + kw)*64;
            unsigned a[NSL][4];
            #pragma unroll
            for (int s = 0; s < NSL; ++s) {
                uint2 lo = *(const uint2*)(ab + s*SLICE);
                uint2 hi = *(const uint2*)(ab + s*SLICE + 8*PS);
                a[s][0] = lo.x; a[s][1] = hi.x;
                a[s][2] = lo.y; a[s][3] = hi.y;
            }
            unsigned b[3][2];
            #pragma unroll
            for (int kd = 0; kd < 3; ++kd) {
                const unsigned* wp = wb + kd*9*64 + tig*8 + gid;
                b[kd][0] = wp[0];
                b[kd][1] = wp[32];
            }
            #pragma unroll
            for (int kd = 0; kd < 3; ++kd)
                #pragma unroll
                for (int o = 0; o < DS; ++o)
                    mma_tf32(acc[o], a[o+kd], b[kd]);
        }
    }

    if (STAGE == 1) {
        const float b0 = bias[2*tig], b1 = bias[2*tig+1];
        #pragma unroll
        for (int o = 0; o < DS; ++o) {
            int d = d0 + o;
            float* row = out + (((size_t)d*HH + (h0+ty))*WW + w0)*8;
            float2 v0 = make_float2(fmaxf(acc[o][0] + b0, 0.f), fmaxf(acc[o][1] + b1, 0.f));
            float2 v1 = make_float2(fmaxf(acc[o][2] + b0, 0.f), fmaxf(acc[o][3] + b1, 0.f));
            *(float2*)(row + gid*8     + 2*tig) = v0;
            *(float2*)(row + (gid+8)*8 + 2*tig) = v1;
        }
    } else {
        const float b0 = bias[0];
        if (tig == 0) {
            #pragma unroll
            for (int o = 0; o < DS; ++o) {
                int d = d0 + o;
                float* row = out + ((size_t)d*HH + (h0+ty))*WW + w0;
                row[gid]   = acc[o][0] + b0;
                row[gid+8] = acc[o][2] + b0;
            }
        }
    }
}

// ---------------------------------------------------------------------------
// Kernel 7: softmax over D + expected depth + 4-tap confidence
// ---------------------------------------------------------------------------
__global__ void k_softmax(const float* __restrict__ dvals, float* __restrict__ out) {
    int p = blockIdx.x*blockDim.x + threadIdx.x;
    if (p >= HW) return;
    float c[DD];
    float m = -1e30f;
    #pragma unroll
    for (int d = 0; d < DD; ++d) { c[d] = g_cost[(size_t)d*HW + p]; m = fmaxf(m, c[d]); }
    float S = 0.f;
    #pragma unroll
    for (int d = 0; d < DD; ++d) { c[d] = expf(c[d] - m); S += c[d]; }
    float inv = 1.0f / S;
    float depth = 0.f, fid = 0.f;
    #pragma unroll
    for (int d = 0; d < DD; ++d) {
        float pr = c[d] * inv;
        depth = fmaf(pr, dvals[(size_t)d*HW + p], depth);
        fid   = fmaf(pr, (float)d, fid);
    }
    int di = (int)fid;
    di = max(0, min(DD-1, di));
    float conf = 0.f;
    #pragma unroll
    for (int d = 0; d < DD; ++d)
        if (d >= di-1 && d <= di+2) conf += c[d] * inv;
    out[p]      = depth;
    out[HW + p] = conf;
}

// ---------------------------------------------------------------------------
// Launch
// ---------------------------------------------------------------------------
extern "C" void kernel_launch(void* const* d_in, const int* in_sizes, int n_in,
                              void* d_out, int out_size) {
    const float* features = (const float*)d_in[0];
    const float* proj     = (const float*)d_in[1];
    const float* dvals    = (const float*)d_in[2];
    const float* w0 = (const float*)d_in[3];
    const float* b0 = (const float*)d_in[4];
    const float* w1 = (const float*)d_in[5];
    const float* b1 = (const float*)d_in[6];
    const float* w2 = (const float*)d_in[7];
    const float* b2 = (const float*)d_in[8];
    float* out = (float*)d_out;

    const int smem0  = 4*5760*4;                 //  92160 B (slab only)
    const int smem12 = (27*64 + 8*1440) * 4;     //  52992 B
    cudaFuncSetAttribute(k_conv0,   cudaFuncAttributeMaxDynamicSharedMemorySize, smem0);
    cudaFuncSetAttribute(k_conv<1>, cudaFuncAttributeMaxDynamicSharedMemorySize, smem12);
    cudaFuncSetAttribute(k_conv<2>, cudaFuncAttributeMaxDynamicSharedMemorySize, smem12);

    k_xform<<<1, 1>>>(proj);
    k_wprep<<<27, 256>>>(w0);
    dim3 tgrid(HW/32, VV);
    k_transpose<<<tgrid, dim3(32, 8)>>>(features);
    k_warpvar<<<DHW/256, 256>>>(dvals);

    dim3 cgrid0(WW/16, HH/8, DD/2);   // (10, 16, 24)
    dim3 cgrid12(WW/16, HH/8, DD/6);  // (10, 16, 8)
    k_conv0<<<cgrid0, 256, smem0>>>(w0, b0);
    k_conv<1><<<cgrid12, 256, smem12>>>(w1, b1);
    k_conv<2><<<cgrid12, 256, smem12>>>(w2, b2);

    k_softmax<<<(HW + 255)/256, 256>>>(dvals, out);
}